// round 4
// baseline (speedup 1.0000x reference)
#include <cuda_runtime.h>
#include <math.h>

#define BB   2
#define SS   2048
#define HH   16
#define DK   64
#define DM   1024
#define TOK  (BB*SS)   // 4096
#define BH   (BB*HH)   // 32

// Scratch (__device__ globals: allocation-free rule)
__device__ float g_rq[(size_t)TOK*DM];      // tf32-rounded Q input
__device__ float g_rk[(size_t)TOK*DM];
__device__ float g_rv[(size_t)TOK*DM];
__device__ float g_rw[(size_t)4*DM*DM];     // tf32-rounded Wq,Wk,Wv,Wo
__device__ float g_q[(size_t)BH*SS*DK];     // projected heads (tf32-rounded)
__device__ float g_k[(size_t)BH*SS*DK];
__device__ float g_v[(size_t)BH*SS*DK];
__device__ float g_ctx[(size_t)TOK*DM];     // attention output (tf32-rounded)

// ---------------------------------------------------------------------------
// helpers
// ---------------------------------------------------------------------------
__device__ __forceinline__ unsigned f2tf(float x) {
    unsigned r;
    asm("cvt.rna.tf32.f32 %0, %1;" : "=r"(r) : "f"(x));
    return r;
}

__device__ __forceinline__ void mma_tf32(float c[4], const unsigned a[4],
                                         unsigned b0, unsigned b1) {
    asm volatile(
        "mma.sync.aligned.m16n8k8.row.col.f32.tf32.tf32.f32 "
        "{%0,%1,%2,%3}, {%4,%5,%6,%7}, {%8,%9}, {%0,%1,%2,%3};"
        : "+f"(c[0]), "+f"(c[1]), "+f"(c[2]), "+f"(c[3])
        : "r"(a[0]), "r"(a[1]), "r"(a[2]), "r"(a[3]), "r"(b0), "r"(b1));
}

__device__ __forceinline__ void cp16(unsigned dst, const void* src) {
    asm volatile("cp.async.cg.shared.global [%0], [%1], 16;\n"
                 :: "r"(dst), "l"(src));
}
__device__ __forceinline__ void cp_commit() {
    asm volatile("cp.async.commit_group;\n");
}
template<int N>
__device__ __forceinline__ void cp_wait() {
    asm volatile("cp.async.wait_group %0;\n" :: "n"(N));
}

// ---------------------------------------------------------------------------
// Elementwise tf32 rounding pass (float4 per thread).
// ---------------------------------------------------------------------------
__global__ __launch_bounds__(256) void round4(
    const float* __restrict__ in, float* __restrict__ out, int n4)
{
    int i = blockIdx.x * blockDim.x + threadIdx.x;
    if (i < n4) {
        float4 v = ((const float4*)in)[i];
        uint4 r = make_uint4(f2tf(v.x), f2tf(v.y), f2tf(v.z), f2tf(v.w));
        ((uint4*)out)[i] = r;
    }
}

// ---------------------------------------------------------------------------
// C = A @ B^T (+bias). A:[M,K], B:[N,K], both tf32-pre-rounded.
// MODE 0: C row-major [M,N] (plain fp32).
// MODE 1: scatter to [bh,s,dk] head layout, values tf32-rounded on write.
// 128x128 tile, BK=32, 256 thr (8 warps 4x2, 32x64/warp), cp.async 2-stage.
// ---------------------------------------------------------------------------
#define GASZ (128*36)
template<int MODE>
__global__ __launch_bounds__(256) void gemm_tf32(
    const float* __restrict__ A, const float* __restrict__ Bm,
    const float* __restrict__ bias, float* __restrict__ C,
    int M, int N, int K)
{
    extern __shared__ float smemf[];
    float* Asm = smemf;             // [2][128*36]
    float* Bsm = smemf + 2*GASZ;

    const int t    = threadIdx.x;
    const int lane = t & 31, wid = t >> 5;
    const int g    = lane >> 2, tig = lane & 3;
    const int wm   = (wid & 3) * 32;
    const int wn   = (wid >> 2) * 64;
    const int bm   = blockIdx.y * 128;
    const int bn   = blockIdx.x * 128;

    const int lrow = t >> 1;
    const int lcol = (t & 1) * 16;

    const float* Ag = A  + (size_t)(bm + lrow) * K + lcol;
    const float* Bg = Bm + (size_t)(bn + lrow) * K + lcol;
    const unsigned sA = (unsigned)__cvta_generic_to_shared(Asm) + (lrow*36 + lcol)*4;
    const unsigned sB = (unsigned)__cvta_generic_to_shared(Bsm) + (lrow*36 + lcol)*4;

    float acc[2][8][4];
#pragma unroll
    for (int mi = 0; mi < 2; mi++)
#pragma unroll
        for (int nj = 0; nj < 8; nj++)
#pragma unroll
            for (int x = 0; x < 4; x++) acc[mi][nj][x] = 0.f;

    // prefetch tile 0 into stage 0
#pragma unroll
    for (int i = 0; i < 4; i++) {
        cp16(sA + i*16, Ag + i*4);
        cp16(sB + i*16, Bg + i*4);
    }
    cp_commit();

    const int NIT = K / 32;
    int s = 0;
    for (int it = 0; it < NIT; it++) {
        if (it + 1 < NIT) {
            const int k0 = (it + 1) * 32;
            const unsigned off = (s ^ 1) * GASZ * 4;
#pragma unroll
            for (int i = 0; i < 4; i++) {
                cp16(sA + off + i*16, Ag + k0 + i*4);
                cp16(sB + off + i*16, Bg + k0 + i*4);
            }
            cp_commit();
            cp_wait<1>();
        } else {
            cp_wait<0>();
        }
        __syncthreads();

        const unsigned* As = (const unsigned*)(Asm + s*GASZ);
        const unsigned* Bs = (const unsigned*)(Bsm + s*GASZ);
#pragma unroll
        for (int k8 = 0; k8 < 4; k8++) {
            const int kk = k8 * 8;
            unsigned a[2][4], b[8][2];
#pragma unroll
            for (int mi = 0; mi < 2; mi++) {
                const int r = wm + mi * 16;
                a[mi][0] = As[(r + g    )*36 + kk + tig];
                a[mi][1] = As[(r + g + 8)*36 + kk + tig];
                a[mi][2] = As[(r + g    )*36 + kk + tig + 4];
                a[mi][3] = As[(r + g + 8)*36 + kk + tig + 4];
            }
#pragma unroll
            for (int nj = 0; nj < 8; nj++) {
                const int r = wn + nj * 8 + g;
                b[nj][0] = Bs[r*36 + kk + tig];
                b[nj][1] = Bs[r*36 + kk + tig + 4];
            }
#pragma unroll
            for (int mi = 0; mi < 2; mi++)
#pragma unroll
                for (int nj = 0; nj < 8; nj++)
                    mma_tf32(acc[mi][nj], a[mi], b[nj][0], b[nj][1]);
        }
        __syncthreads();
        s ^= 1;
    }

#pragma unroll
    for (int mi = 0; mi < 2; mi++) {
#pragma unroll
        for (int nj = 0; nj < 8; nj++) {
            const int col = bn + wn + nj * 8 + 2 * tig;
            const float bx = bias ? bias[col]     : 0.f;
            const float by = bias ? bias[col + 1] : 0.f;
            const int r0 = bm + wm + mi * 16 + g;
            const int r1 = r0 + 8;
            if (MODE == 0) {
                *(float2*)(C + (size_t)r0 * N + col) =
                    make_float2(acc[mi][nj][0] + bx, acc[mi][nj][1] + by);
                *(float2*)(C + (size_t)r1 * N + col) =
                    make_float2(acc[mi][nj][2] + bx, acc[mi][nj][3] + by);
            } else {
                const int h_ = col >> 6, d_ = col & 63;
                float2 v0 = make_float2(
                    __uint_as_float(f2tf(acc[mi][nj][0] + bx)),
                    __uint_as_float(f2tf(acc[mi][nj][1] + by)));
                float2 v1 = make_float2(
                    __uint_as_float(f2tf(acc[mi][nj][2] + bx)),
                    __uint_as_float(f2tf(acc[mi][nj][3] + by)));
                {
                    const int b_ = r0 >> 11, s_ = r0 & 2047;
                    *(float2*)(C + ((size_t)((b_*HH + h_)*SS + s_))*DK + d_) = v0;
                }
                {
                    const int b_ = r1 >> 11, s_ = r1 & 2047;
                    *(float2*)(C + ((size_t)((b_*HH + h_)*SS + s_))*DK + d_) = v1;
                }
            }
        }
    }
}

// ---------------------------------------------------------------------------
// Fused flash attention. grid=(S/128, BH), 256 thr (8 warps x 16 q rows).
// KV tiles of 64, cp.async double-buffered, base-2 online softmax.
// All operands pre-rounded tf32. Output tf32-rounded -> ctx [B,S,DM].
// smem: K[2][64*68] | V[2][64*68] interleaved per stage | P[8][16*68]
//   stage s: K at s*8704, V at s*8704+4352; P at 17408. Total 26112 floats.
// ---------------------------------------------------------------------------
__global__ __launch_bounds__(256, 2) void flash_attn(
    const float* __restrict__ q, const float* __restrict__ k,
    const float* __restrict__ v, float* __restrict__ ctx)
{
    extern __shared__ float smf[];

    const int t    = threadIdx.x;
    const int lane = t & 31, wid = t >> 5;
    const int g    = lane >> 2, tig = lane & 3;
    const int bh   = blockIdx.y;
    const int q0   = blockIdx.x * 128;

    // Q fragments, scaled by (1/sqrt(dk)) * log2(e) for base-2 softmax
    const float QSC = 0.125f * 1.4426950408889634f;
    const float* qb = q + ((size_t)bh * SS + q0 + wid * 16) * DK;
    unsigned aq[8][4];
#pragma unroll
    for (int k8 = 0; k8 < 8; k8++) {
        aq[k8][0] = f2tf(qb[(size_t)g       * DK + k8*8 + tig    ] * QSC);
        aq[k8][1] = f2tf(qb[(size_t)(g + 8) * DK + k8*8 + tig    ] * QSC);
        aq[k8][2] = f2tf(qb[(size_t)g       * DK + k8*8 + tig + 4] * QSC);
        aq[k8][3] = f2tf(qb[(size_t)(g + 8) * DK + k8*8 + tig + 4] * QSC);
    }

    float o[8][4];
#pragma unroll
    for (int nj = 0; nj < 8; nj++)
#pragma unroll
        for (int x = 0; x < 4; x++) o[nj][x] = 0.f;
    float mrun0 = -1e30f, mrun1 = -1e30f, l0 = 0.f, l1 = 0.f;

    const float* kb = k + (size_t)bh * SS * DK;
    const float* vb = v + (size_t)bh * SS * DK;

    // cp.async mapping: 64 rows x 64 cols per tile; thread t -> row t>>2,
    // 4 chunks of 4 floats at cols (t&3)*16 + 4i
    const int crow = t >> 2;
    const int ccol = (t & 3) * 16;
    const unsigned sbase = (unsigned)__cvta_generic_to_shared(smf);
    const unsigned sK = sbase + (crow*68 + ccol)*4;
    const unsigned sV = sbase + (4352 + crow*68 + ccol)*4;

    unsigned* PsW = (unsigned*)(smf + 17408) + wid * 16 * 68;

    // prefetch tile 0 -> stage 0
    {
        const float* kr = kb + (size_t)crow * DK + ccol;
        const float* vr = vb + (size_t)crow * DK + ccol;
#pragma unroll
        for (int i = 0; i < 4; i++) {
            cp16(sK + i*16, kr + i*4);
            cp16(sV + i*16, vr + i*4);
        }
        cp_commit();
    }

    int s = 0;
    for (int kt = 0; kt < SS / 64; kt++) {
        if (kt + 1 < SS / 64) {
            const unsigned off = (s ^ 1) * 8704 * 4;
            const float* kr = kb + (size_t)((kt+1)*64 + crow) * DK + ccol;
            const float* vr = vb + (size_t)((kt+1)*64 + crow) * DK + ccol;
#pragma unroll
            for (int i = 0; i < 4; i++) {
                cp16(sK + off + i*16, kr + i*4);
                cp16(sV + off + i*16, vr + i*4);
            }
            cp_commit();
            cp_wait<1>();
        } else {
            cp_wait<0>();
        }
        __syncthreads();

        const unsigned* Ks = (const unsigned*)(smf + s*8704);
        const unsigned* Vs = (const unsigned*)(smf + s*8704 + 4352);

        // S = Q @ K^T (log2-scaled)
        float sacc[8][4];
#pragma unroll
        for (int nj = 0; nj < 8; nj++)
#pragma unroll
            for (int x = 0; x < 4; x++) sacc[nj][x] = 0.f;
#pragma unroll
        for (int k8 = 0; k8 < 8; k8++) {
#pragma unroll
            for (int nj = 0; nj < 8; nj++) {
                unsigned b0 = Ks[(nj*8 + g)*68 + k8*8 + tig];
                unsigned b1 = Ks[(nj*8 + g)*68 + k8*8 + tig + 4];
                mma_tf32(sacc[nj], aq[k8], b0, b1);
            }
        }

        // base-2 online softmax (rows g and g+8)
        float mx0 = -1e30f, mx1 = -1e30f;
#pragma unroll
        for (int nj = 0; nj < 8; nj++) {
            mx0 = fmaxf(mx0, fmaxf(sacc[nj][0], sacc[nj][1]));
            mx1 = fmaxf(mx1, fmaxf(sacc[nj][2], sacc[nj][3]));
        }
        mx0 = fmaxf(mx0, __shfl_xor_sync(0xffffffffu, mx0, 1));
        mx0 = fmaxf(mx0, __shfl_xor_sync(0xffffffffu, mx0, 2));
        mx1 = fmaxf(mx1, __shfl_xor_sync(0xffffffffu, mx1, 1));
        mx1 = fmaxf(mx1, __shfl_xor_sync(0xffffffffu, mx1, 2));

        const float mn0 = fmaxf(mrun0, mx0), mn1 = fmaxf(mrun1, mx1);
        const float al0 = exp2f(mrun0 - mn0), al1 = exp2f(mrun1 - mn1);
        float s0 = 0.f, s1 = 0.f;
#pragma unroll
        for (int nj = 0; nj < 8; nj++) {
            float p0 = exp2f(sacc[nj][0] - mn0);
            float p1 = exp2f(sacc[nj][1] - mn0);
            float p2 = exp2f(sacc[nj][2] - mn1);
            float p3 = exp2f(sacc[nj][3] - mn1);
            s0 += p0 + p1; s1 += p2 + p3;
            unsigned* pr0 = PsW + (size_t)g        * 68 + nj*8 + 2*tig;
            unsigned* pr1 = PsW + (size_t)(g + 8)  * 68 + nj*8 + 2*tig;
            pr0[0] = f2tf(p0); pr0[1] = f2tf(p1);
            pr1[0] = f2tf(p2); pr1[1] = f2tf(p3);
            o[nj][0] *= al0; o[nj][1] *= al0;
            o[nj][2] *= al1; o[nj][3] *= al1;
        }
        s0 += __shfl_xor_sync(0xffffffffu, s0, 1);
        s0 += __shfl_xor_sync(0xffffffffu, s0, 2);
        s1 += __shfl_xor_sync(0xffffffffu, s1, 1);
        s1 += __shfl_xor_sync(0xffffffffu, s1, 2);
        l0 = l0 * al0 + s0;
        l1 = l1 * al1 + s1;
        mrun0 = mn0; mrun1 = mn1;
        __syncwarp();

        // O += P @ V
#pragma unroll
        for (int k8 = 0; k8 < 8; k8++) {
            unsigned ap[4];
            ap[0] = PsW[(size_t)g       * 68 + k8*8 + tig];
            ap[1] = PsW[(size_t)(g + 8) * 68 + k8*8 + tig];
            ap[2] = PsW[(size_t)g       * 68 + k8*8 + tig + 4];
            ap[3] = PsW[(size_t)(g + 8) * 68 + k8*8 + tig + 4];
#pragma unroll
            for (int nj = 0; nj < 8; nj++) {
                unsigned b0 = Vs[(k8*8 + tig    )*68 + nj*8 + g];
                unsigned b1 = Vs[(k8*8 + tig + 4)*68 + nj*8 + g];
                mma_tf32(o[nj], ap, b0, b1);
            }
        }
        __syncthreads();   // stage s free before next prefetch overwrites it
        s ^= 1;
    }

    // write ctx [B,S,DM], tf32-rounded (feeds final GEMM directly)
    const float inv0 = 1.f / l0, inv1 = 1.f / l1;
    const int b_ = bh >> 4, h_ = bh & 15;
    const int r0 = q0 + wid * 16 + g;
    float* cb = ctx + (size_t)b_ * SS * DM + (size_t)h_ * DK;
#pragma unroll
    for (int nj = 0; nj < 8; nj++) {
        const int col = nj * 8 + 2 * tig;
        *(float2*)(cb + (size_t)r0       * DM + col) = make_float2(
            __uint_as_float(f2tf(o[nj][0] * inv0)),
            __uint_as_float(f2tf(o[nj][1] * inv0)));
        *(float2*)(cb + (size_t)(r0 + 8) * DM + col) = make_float2(
            __uint_as_float(f2tf(o[nj][2] * inv1)),
            __uint_as_float(f2tf(o[nj][3] * inv1)));
    }
}

// ---------------------------------------------------------------------------
extern "C" void kernel_launch(void* const* d_in, const int* in_sizes, int n_in,
                              void* d_out, int out_size)
{
    const float* Q  = (const float*)d_in[0];
    const float* Kx = (const float*)d_in[1];
    const float* Vx = (const float*)d_in[2];
    const float* Wq = (const float*)d_in[3];
    const float* bq = (const float*)d_in[4];
    const float* Wk = (const float*)d_in[5];
    const float* bk = (const float*)d_in[6];
    const float* Wv = (const float*)d_in[7];
    const float* bv = (const float*)d_in[8];
    const float* Wo = (const float*)d_in[9];
    const float* bo = (const float*)d_in[10];
    float* out = (float*)d_out;

    float *rq, *rk, *rv, *rw, *gq, *gk, *gv, *gc;
    cudaGetSymbolAddress((void**)&rq, g_rq);
    cudaGetSymbolAddress((void**)&rk, g_rk);
    cudaGetSymbolAddress((void**)&rv, g_rv);
    cudaGetSymbolAddress((void**)&rw, g_rw);
    cudaGetSymbolAddress((void**)&gq, g_q);
    cudaGetSymbolAddress((void**)&gk, g_k);
    cudaGetSymbolAddress((void**)&gv, g_v);
    cudaGetSymbolAddress((void**)&gc, g_ctx);

    static bool attr_set = false;
    if (!attr_set) {
        cudaFuncSetAttribute(flash_attn,
            cudaFuncAttributeMaxDynamicSharedMemorySize, 26112 * 4);
        cudaFuncSetAttribute(gemm_tf32<0>,
            cudaFuncAttributeMaxDynamicSharedMemorySize, 4 * GASZ * 4);
        cudaFuncSetAttribute(gemm_tf32<1>,
            cudaFuncAttributeMaxDynamicSharedMemorySize, 4 * GASZ * 4);
        attr_set = true;
    }

    dim3 blk(256);
    const int gemm_smem = 4 * GASZ * 4;   // 73728 B

    // 0) pre-round everything to tf32
    const int nAct4 = TOK * DM / 4;       // 1,048,576
    const int nW4   = DM * DM / 4;        // 262,144
    round4<<<nAct4 / 256, blk>>>(Q,  rq, nAct4);
    round4<<<nAct4 / 256, blk>>>(Kx, rk, nAct4);
    round4<<<nAct4 / 256, blk>>>(Vx, rv, nAct4);
    round4<<<nW4 / 256, blk>>>(Wq, rw + 0*(size_t)DM*DM, nW4);
    round4<<<nW4 / 256, blk>>>(Wk, rw + 1*(size_t)DM*DM, nW4);
    round4<<<nW4 / 256, blk>>>(Wv, rw + 2*(size_t)DM*DM, nW4);
    round4<<<nW4 / 256, blk>>>(Wo, rw + 3*(size_t)DM*DM, nW4);

    // 1) projections -> [bh, s, dk] (tf32-rounded on write)
    dim3 gproj(DM / 128, TOK / 128);
    gemm_tf32<1><<<gproj, blk, gemm_smem>>>(rq, rw + 0*(size_t)DM*DM, bq, gq, TOK, DM, DM);
    gemm_tf32<1><<<gproj, blk, gemm_smem>>>(rk, rw + 1*(size_t)DM*DM, bk, gk, TOK, DM, DM);
    gemm_tf32<1><<<gproj, blk, gemm_smem>>>(rv, rw + 2*(size_t)DM*DM, bv, gv, TOK, DM, DM);

    // 2) fused attention -> ctx [B,S,DM]
    dim3 gfa(SS / 128, BH);
    flash_attn<<<gfa, blk, 26112 * 4>>>(gq, gk, gv, gc);

    // 3) out = ctx @ Wo^T + bo
    dim3 gout(DM / 128, TOK / 128);
    gemm_tf32<0><<<gout, blk, gemm_smem>>>(gc, rw + 3*(size_t)DM*DM, bo, out, TOK, DM, DM);
}